// round 15
// baseline (speedup 1.0000x reference)
#include <cuda_runtime.h>
#include <cstdint>

// DCN cross, B=8192, D=256, L=4 — collapsed algebra + TMA bulk-load of x:
//   out = a_L*x0 + v_L,  a_{l+1} = a_l*(1+d_l) + c_l,  d_l = x0.W_l
// Per block: ONE cp.async.bulk (16 KB, 16 contiguous rows) into smem instead of
// 64 scattered LDG.128 — bulk DMA bypasses the L1tex wavefront/latency path.
// Compute mapping unchanged from R7: 16 lanes/row, 2 rows/warp, 8 warps/block.

constexpr int D = 256;
constexpr int L = 4;
constexpr int ROWS_PER_BLOCK = 16;
constexpr unsigned TILE_BYTES = ROWS_PER_BLOCK * D * 4;   // 16384

__global__ __launch_bounds__(256)
void cross_kernel(const float* __restrict__ x,
                  const float* __restrict__ W,
                  const float* __restrict__ b_lin,
                  const float* __restrict__ bias,
                  float* __restrict__ out)
{
    __shared__ alignas(16) float x_tile[ROWS_PER_BLOCK * D];  // 16 KB
    __shared__ float W_sm[L * D];                             // 4 KB
    __shared__ float v_sm[D];                                 // 1 KB
    __shared__ float4 c_part[8];
    __shared__ alignas(8) uint64_t mbar;

    const int tid  = threadIdx.x;
    const int warp = tid >> 5;
    const int lane = tid & 31;
    const int j    = lane & 15;                 // slot within 16-lane row group
    const int lrow = warp * 2 + (lane >> 4);    // local row 0..15
    const int row  = blockIdx.x * ROWS_PER_BLOCK + lrow;

    const uint32_t mbar_a = (uint32_t)__cvta_generic_to_shared(&mbar);
    const uint32_t xt_a   = (uint32_t)__cvta_generic_to_shared(x_tile);

    // ---- init mbarrier, then kick the bulk DMA for this block's 16 rows ----
    if (tid == 0)
        asm volatile("mbarrier.init.shared.b64 [%0], %1;" :: "r"(mbar_a), "r"(1u) : "memory");
    __syncthreads();
    if (tid == 0) {
        const float* src = x + (size_t)blockIdx.x * ROWS_PER_BLOCK * D;
        asm volatile("mbarrier.arrive.expect_tx.shared.b64 _, [%0], %1;"
                     :: "r"(mbar_a), "r"(TILE_BYTES) : "memory");
        asm volatile("cp.async.bulk.shared::cluster.global.mbarrier::complete_tx::bytes "
                     "[%0], [%1], %2, [%3];"
                     :: "r"(xt_a), "l"(src), "r"(TILE_BYTES), "r"(mbar_a) : "memory");
    }

    // ---- preamble overlaps the DMA: W->smem, v_L, per-warp c partials ----
    {
        float v = 0.0f;
        float cp[L];
        #pragma unroll
        for (int l = 0; l < L; ++l) {
            const float w = W[l * D + tid];
            W_sm[l * D + tid] = w;
            cp[l] = v * w;                        // c_l uses v BEFORE update
            v += b_lin[l] + bias[l * D + tid];
        }
        v_sm[tid] = v;
        #pragma unroll
        for (int o = 16; o > 0; o >>= 1) {
            #pragma unroll
            for (int l = 0; l < L; ++l)
                cp[l] += __shfl_xor_sync(0xffffffffu, cp[l], o);
        }
        if (lane == 0)
            c_part[warp] = make_float4(cp[0], cp[1], cp[2], cp[3]);
    }
    __syncthreads();                              // publishes W_sm, v_sm, c_part

    // fold c partials per thread (broadcast LDS)
    float c[L];
    {
        float4 c0 = c_part[0], c1 = c_part[1], c2 = c_part[2], c3 = c_part[3];
        float4 c4 = c_part[4], c5 = c_part[5], c6 = c_part[6], c7 = c_part[7];
        c[0] = ((c0.x + c1.x) + (c2.x + c3.x)) + ((c4.x + c5.x) + (c6.x + c7.x));
        c[1] = ((c0.y + c1.y) + (c2.y + c3.y)) + ((c4.y + c5.y) + (c6.y + c7.y));
        c[2] = ((c0.z + c1.z) + (c2.z + c3.z)) + ((c4.z + c5.z) + (c6.z + c7.z));
        c[3] = ((c0.w + c1.w) + (c2.w + c3.w)) + ((c4.w + c5.w) + (c6.w + c7.w));
    }

    // ---- wait for the x tile (acquire) ----
    asm volatile(
        "{\n\t.reg .pred P1;\n\t"
        "LAB_%=:\n\t"
        "mbarrier.try_wait.parity.acquire.cta.shared::cta.b64 P1, [%0], %1, 0x989680;\n\t"
        "@!P1 bra LAB_%=;\n\t"
        "}" :: "r"(mbar_a), "r"(0u) : "memory");

    // ---- x from smem into registers (4x LDS.128 per lane) ----
    const float4* xt = reinterpret_cast<const float4*>(x_tile) + lrow * (D / 4);
    float4 xq[4];
    #pragma unroll
    for (int k = 0; k < 4; ++k) xq[k] = xt[k * 16 + j];

    // ---- dots: d_l = x0 . W_l (W broadcast from smem) ----
    const float4* Wv = reinterpret_cast<const float4*>(W_sm);
    float d[L];
    #pragma unroll
    for (int l = 0; l < L; ++l) {
        float a0 = 0.f, a1 = 0.f, a2 = 0.f, a3 = 0.f;
        #pragma unroll
        for (int k = 0; k < 4; ++k) {
            const float4 w = Wv[l * 64 + k * 16 + j];
            a0 = fmaf(xq[k].x, w.x, a0);
            a1 = fmaf(xq[k].y, w.y, a1);
            a2 = fmaf(xq[k].z, w.z, a2);
            a3 = fmaf(xq[k].w, w.w, a3);
        }
        d[l] = (a0 + a1) + (a2 + a3);
    }

    // ---- 4-step width-16 ladder: one SHFL reduces both rows of the warp ----
    #pragma unroll
    for (int o = 8; o > 0; o >>= 1) {
        #pragma unroll
        for (int l = 0; l < L; ++l)
            d[l] += __shfl_xor_sync(0xffffffffu, d[l], o);
    }

    // ---- scalar recurrence: a += a*d_l + c_l ----
    float a = 1.0f;
    #pragma unroll
    for (int l = 0; l < L; ++l)
        a = fmaf(a, d[l], a + c[l]);

    // ---- epilogue: out = a*x0 + v_L (direct STG.128) ----
    const float4* vr = reinterpret_cast<const float4*>(v_sm);
    float4* orow = reinterpret_cast<float4*>(out + (size_t)row * D);
    #pragma unroll
    for (int k = 0; k < 4; ++k) {
        const float4 v = vr[k * 16 + j];
        float4 o4;
        o4.x = fmaf(a, xq[k].x, v.x);
        o4.y = fmaf(a, xq[k].y, v.y);
        o4.z = fmaf(a, xq[k].z, v.z);
        o4.w = fmaf(a, xq[k].w, v.w);
        orow[k * 16 + j] = o4;
    }
}

extern "C" void kernel_launch(void* const* d_in, const int* in_sizes, int n_in,
                              void* d_out, int out_size)
{
    const float* x     = (const float*)d_in[0];
    const float* W     = (const float*)d_in[1];
    const float* b_lin = (const float*)d_in[2];
    const float* bias  = (const float*)d_in[3];
    float* out         = (float*)d_out;

    const int B = in_sizes[0] / D;                                // 8192
    const int blocks = (B + ROWS_PER_BLOCK - 1) / ROWS_PER_BLOCK; // 512

    cross_kernel<<<blocks, 256>>>(x, W, b_lin, bias, out);
}